// round 14
// baseline (speedup 1.0000x reference)
#include <cuda_runtime.h>
#include <cuda_bf16.h>
#include <stdint.h>

#define N_NODES  50000
#define N_EDGES  800000
#define F        128
#define N_GRAPHS 128
#define N_CLASSES 10

// ---------------- scratch (no allocations allowed) ----------------
__device__ __align__(16) short g_Hq[N_NODES * F];    // quantized GEMM output
__device__ float g_hscale[N_NODES];                  // per-row dequant scale
__device__ __align__(16) float g_ACC[N_NODES * F];   // aggregated layer output
__device__ float g_dinv[N_NODES];
__device__ int   g_degi[N_NODES];
__device__ int   g_rowbeg[N_NODES];
__device__ int   g_cursor[N_NODES];
__device__ int   g_alloc;
__device__ int   g_csrc[N_EDGES];
__device__ float g_cnorm[N_EDGES];
__device__ float g_cnorm2[N_EDGES];                  // cnorm * hscale[src] (per layer)
__device__ __align__(16) float g_gsum[N_GRAPHS * F];
__device__ float g_gcnt[N_GRAPHS];

__device__ __forceinline__ void red_add_v4(float* p, float4 v) {
    asm volatile("red.relaxed.gpu.global.add.v4.f32 [%0], {%1, %2, %3, %4};"
                 :: "l"(p), "f"(v.x), "f"(v.y), "f"(v.z), "f"(v.w)
                 : "memory");
}

// ---------------- packed f32x2 helpers (Blackwell FFMA2) ----------------
__device__ __forceinline__ unsigned long long pack2(float lo, float hi) {
    unsigned long long r;
    asm("mov.b64 %0, {%1, %2};" : "=l"(r) : "f"(lo), "f"(hi));
    return r;
}
__device__ __forceinline__ void fma2(unsigned long long& d,
                                     unsigned long long a, unsigned long long b) {
    asm("fma.rn.f32x2 %0, %1, %2, %0;" : "+l"(d) : "l"(a), "l"(b));
}
__device__ __forceinline__ float2 unpack2(unsigned long long v) {
    float2 r;
    asm("mov.b64 {%0, %1}, %2;" : "=f"(r.x), "=f"(r.y) : "l"(v));
    return r;
}

// ---------------- precompute ----------------
__global__ void k_init(const int* __restrict__ batch) {
    int i = blockIdx.x * blockDim.x + threadIdx.x;
    if (i < N_NODES) {
        g_degi[i] = 0;
        atomicAdd(&g_gcnt[batch[i]], 1.0f);
    }
    if (i < N_GRAPHS * F) g_gsum[i] = 0.0f;
    if (i == 0) g_alloc = 0;
}

__global__ void k_zero_cnt() {
    int i = threadIdx.x;
    if (i < N_GRAPHS) g_gcnt[i] = 0.0f;
}

__global__ void k_deg(const int* __restrict__ ei) {
    int e = blockIdx.x * blockDim.x + threadIdx.x;
    if (e < N_EDGES) atomicAdd(&g_degi[ei[N_EDGES + e]], 1);
}

// warp-aggregated segment allocation: one global atomic per warp
__global__ void k_alloc_seg() {
    int i    = blockIdx.x * blockDim.x + threadIdx.x;
    int lane = threadIdx.x & 31;
    int deg  = (i < N_NODES) ? g_degi[i] : 0;
    int scan = deg;
    #pragma unroll
    for (int o = 1; o < 32; o <<= 1) {
        int t = __shfl_up_sync(0xFFFFFFFFu, scan, o);
        if (lane >= o) scan += t;
    }
    int total = __shfl_sync(0xFFFFFFFFu, scan, 31);
    int base = 0;
    if (lane == 31) base = atomicAdd(&g_alloc, total);
    base = __shfl_sync(0xFFFFFFFFu, base, 31);
    if (i < N_NODES) {
        int pos = base + scan - deg;
        g_rowbeg[i] = pos;
        g_cursor[i] = pos;
        g_dinv[i]   = rsqrtf((float)deg + 1.0f);
    }
}

__global__ void k_fill(const int* __restrict__ ei) {
    int e = blockIdx.x * blockDim.x + threadIdx.x;
    if (e < N_EDGES) {
        int s = ei[e];
        int d = ei[N_EDGES + e];
        int pos = atomicAdd(&g_cursor[d], 1);
        g_csrc[pos]  = s;
        g_cnorm[pos] = g_dinv[s] * g_dinv[d];
    }
}

// per-layer: fold the (new) per-row dequant scale into the edge weight,
// removing the dependent hscale gather from the aggregate inner loop.
__global__ void k_premul() {
    int e = blockIdx.x * blockDim.x + threadIdx.x;
    if (e < N_EDGES)
        g_cnorm2[e] = g_cnorm[e] * __ldg(&g_hscale[__ldg(&g_csrc[e])]);
}

// ---------------- GEMM: H = act(X) @ W  (FFMA2, zipped row-pair X) ----------
// Epilogue quantizes each output row to int16 with a per-row scale.
template <int MODE>
__global__ void __launch_bounds__(256, 2)
k_gemm(const float* __restrict__ Xin, const float* __restrict__ W) {
    extern __shared__ float smem[];
    float* sW  = smem;            // [128][128] = 64 KB
    float* sXz = smem + F * F;    // [32 rp][128 k][2] = 32 KB

    const int tid  = threadIdx.x;
    const int row0 = blockIdx.x * 64;

    #pragma unroll
    for (int i = 0; i < 16; i++)
        ((float4*)sW)[tid + i * 256] = ((const float4*)W)[tid + i * 256];

    const float* src = (MODE == 0) ? Xin : g_ACC;
    #pragma unroll
    for (int i = 0; i < 4; i++) {
        int idx = tid + i * 256;          // over 32 k4-groups x 32 row-pairs
        int k4  = idx & 31;
        int rp  = idx >> 5;
        int r0  = row0 + 2 * rp;
        float4 a = make_float4(0.f, 0.f, 0.f, 0.f);
        float4 b = make_float4(0.f, 0.f, 0.f, 0.f);
        if (r0 < N_NODES)     a = ((const float4*)(src + (size_t)r0 * F))[k4];
        if (r0 + 1 < N_NODES) b = ((const float4*)(src + (size_t)(r0 + 1) * F))[k4];
        if (MODE == 1) {
            a.x = fmaxf(a.x, 0.f); a.y = fmaxf(a.y, 0.f);
            a.z = fmaxf(a.z, 0.f); a.w = fmaxf(a.w, 0.f);
            b.x = fmaxf(b.x, 0.f); b.y = fmaxf(b.y, 0.f);
            b.z = fmaxf(b.z, 0.f); b.w = fmaxf(b.w, 0.f);
        }
        float2* dst = (float2*)&sXz[rp * 256 + k4 * 8];
        dst[0] = make_float2(a.x, b.x);
        dst[1] = make_float2(a.y, b.y);
        dst[2] = make_float2(a.z, b.z);
        dst[3] = make_float2(a.w, b.w);
    }
    __syncthreads();

    const int wp = tid >> 5;     // warp 0..7 -> row-pairs 4wp..4wp+3
    const int cg = tid & 31;     // lane -> cols 4cg..4cg+3

    unsigned long long acc[4][4];   // [row-pair][col], pair over rows
    #pragma unroll
    for (int i = 0; i < 4; i++)
        #pragma unroll
        for (int j = 0; j < 4; j++) acc[i][j] = 0ull;

    #pragma unroll 4
    for (int k = 0; k < F; k += 2) {
        float4 wa = *(float4*)&sW[k * F + cg * 4];
        float4 wb = *(float4*)&sW[(k + 1) * F + cg * 4];
        unsigned long long wa0 = pack2(wa.x, wa.x), wa1 = pack2(wa.y, wa.y);
        unsigned long long wa2 = pack2(wa.z, wa.z), wa3 = pack2(wa.w, wa.w);
        unsigned long long wb0 = pack2(wb.x, wb.x), wb1 = pack2(wb.y, wb.y);
        unsigned long long wb2 = pack2(wb.z, wb.z), wb3 = pack2(wb.w, wb.w);
        #pragma unroll
        for (int rp = 0; rp < 4; rp++) {
            ulonglong2 xp = *(const ulonglong2*)&sXz[(4 * wp + rp) * 256 + k * 2];
            fma2(acc[rp][0], xp.x, wa0); fma2(acc[rp][1], xp.x, wa1);
            fma2(acc[rp][2], xp.x, wa2); fma2(acc[rp][3], xp.x, wa3);
            fma2(acc[rp][0], xp.y, wb0); fma2(acc[rp][1], xp.y, wb1);
            fma2(acc[rp][2], xp.y, wb2); fma2(acc[rp][3], xp.y, wb3);
        }
    }

    // epilogue: per-row int16 quantization
    #pragma unroll
    for (int rp = 0; rp < 4; rp++) {
        int r = row0 + 2 * (4 * wp + rp);
        float2 p0 = unpack2(acc[rp][0]);
        float2 p1 = unpack2(acc[rp][1]);
        float2 p2 = unpack2(acc[rp][2]);
        float2 p3 = unpack2(acc[rp][3]);
        float m0 = fmaxf(fmaxf(fabsf(p0.x), fabsf(p1.x)),
                         fmaxf(fabsf(p2.x), fabsf(p3.x)));
        float m1 = fmaxf(fmaxf(fabsf(p0.y), fabsf(p1.y)),
                         fmaxf(fabsf(p2.y), fabsf(p3.y)));
        #pragma unroll
        for (int o = 16; o > 0; o >>= 1) {
            m0 = fmaxf(m0, __shfl_xor_sync(0xFFFFFFFFu, m0, o));
            m1 = fmaxf(m1, __shfl_xor_sync(0xFFFFFFFFu, m1, o));
        }
        float inv0 = (m0 > 0.f) ? 32767.0f / m0 : 0.f;
        float inv1 = (m1 > 0.f) ? 32767.0f / m1 : 0.f;
        if (r < N_NODES) {
            short4 q;
            q.x = (short)__float2int_rn(p0.x * inv0);
            q.y = (short)__float2int_rn(p1.x * inv0);
            q.z = (short)__float2int_rn(p2.x * inv0);
            q.w = (short)__float2int_rn(p3.x * inv0);
            *(short4*)&g_Hq[(size_t)r * F + cg * 4] = q;
            if (cg == 0) g_hscale[r] = m0 * (1.0f / 32767.0f);
        }
        if (r + 1 < N_NODES) {
            short4 q;
            q.x = (short)__float2int_rn(p0.y * inv1);
            q.y = (short)__float2int_rn(p1.y * inv1);
            q.z = (short)__float2int_rn(p2.y * inv1);
            q.w = (short)__float2int_rn(p3.y * inv1);
            *(short4*)&g_Hq[(size_t)(r + 1) * F + cg * 4] = q;
            if (cg == 0) g_hscale[r + 1] = m1 * (1.0f / 32767.0f);
        }
    }
}

// ---------------- aggregate: ACC[d] = sum_in cnorm2*Hq[s] + self + b --------
// cnorm2 already carries hscale[src]; inner loop has NO dependent scale gather.
// POOL=1: RED the result into g_gsum[batch[d]] instead of storing ACC.
template <int POOL>
__global__ void __launch_bounds__(256)
k_aggregate(const float* __restrict__ bias, const int* __restrict__ batch) {
    const int warp = (blockIdx.x * blockDim.x + threadIdx.x) >> 5;
    const int lane = threadIdx.x & 31;
    if (warp >= N_NODES) return;
    const int d = warp;

    const int beg = __ldg(&g_rowbeg[d]);
    const int end = beg + __ldg(&g_degi[d]);
    const float di = __ldg(&g_dinv[d]);

    // self-loop (quantized, scale loaded once per warp)
    float ssc = di * di * __ldg(&g_hscale[d]);
    short4 qs = *(const short4*)&g_Hq[(size_t)d * F + lane * 4];
    float4 acc = make_float4(ssc * (float)qs.x, ssc * (float)qs.y,
                             ssc * (float)qs.z, ssc * (float)qs.w);

    int j = beg;
    if (j < end) {
        int   s0  = __ldg(&g_csrc[j]);
        float sc0 = __ldg(&g_cnorm2[j]);
        short4 q0 = *(const short4*)&g_Hq[(size_t)s0 * F + lane * 4];
        for (j = beg + 1; j < end; j++) {
            int   s1  = __ldg(&g_csrc[j]);
            float sc1 = __ldg(&g_cnorm2[j]);
            short4 q1 = *(const short4*)&g_Hq[(size_t)s1 * F + lane * 4];
            acc.x += sc0 * (float)q0.x; acc.y += sc0 * (float)q0.y;
            acc.z += sc0 * (float)q0.z; acc.w += sc0 * (float)q0.w;
            q0 = q1; sc0 = sc1;
        }
        acc.x += sc0 * (float)q0.x; acc.y += sc0 * (float)q0.y;
        acc.z += sc0 * (float)q0.z; acc.w += sc0 * (float)q0.w;
    }

    float4 bv = *(const float4*)&bias[lane * 4];
    acc.x += bv.x; acc.y += bv.y; acc.z += bv.z; acc.w += bv.w;

    if (POOL) {
        int g = __ldg(&batch[d]);
        red_add_v4(&g_gsum[g * F + lane * 4], acc);
    } else {
        *(float4*)&g_ACC[(size_t)d * F + lane * 4] = acc;
    }
}

// ---------------- head ----------------
__global__ void k_final(const float* __restrict__ lin_w,
                        const float* __restrict__ lin_b,
                        float* __restrict__ out) {
    int g = blockIdx.x;
    int c = threadIdx.x;
    if (c >= N_CLASSES) return;
    float cnt = fmaxf(g_gcnt[g], 1.0f);
    float acc = 0.f;
    #pragma unroll 8
    for (int f = 0; f < F; f++)
        acc += g_gsum[g * F + f] * __ldg(&lin_w[f * N_CLASSES + c]);
    out[g * N_CLASSES + c] = acc / cnt + lin_b[c];
}

// ---------------- host ----------------
extern "C" void kernel_launch(void* const* d_in, const int* in_sizes, int n_in,
                              void* d_out, int out_size) {
    const float* x     = (const float*)d_in[0];
    const int*   ei    = (const int*)d_in[1];
    const int*   batch = (const int*)d_in[2];
    const float* w1 = (const float*)d_in[3];
    const float* b1 = (const float*)d_in[4];
    const float* w2 = (const float*)d_in[5];
    const float* b2 = (const float*)d_in[6];
    const float* w3 = (const float*)d_in[7];
    const float* b3 = (const float*)d_in[8];
    const float* lw = (const float*)d_in[9];
    const float* lb = (const float*)d_in[10];
    float* out = (float*)d_out;

    const int SMEM = (F * F + 64 * F) * (int)sizeof(float);   // 96 KB
    cudaFuncSetAttribute(k_gemm<0>, cudaFuncAttributeMaxDynamicSharedMemorySize, SMEM);
    cudaFuncSetAttribute(k_gemm<1>, cudaFuncAttributeMaxDynamicSharedMemorySize, SMEM);

    const int GB = (N_NODES + 63) / 64;
    const int AB = (N_NODES + 7) / 8;
    const int EB = (N_EDGES + 255) / 256;

    k_zero_cnt<<<1, N_GRAPHS>>>();
    k_init<<<(N_NODES + 255) / 256, 256>>>(batch);
    k_deg<<<EB, 256>>>(ei);
    k_alloc_seg<<<(N_NODES + 255) / 256, 256>>>();
    k_fill<<<EB, 256>>>(ei);

    k_gemm<0><<<GB, 256, SMEM>>>(x, w1);
    k_premul<<<EB, 256>>>();
    k_aggregate<0><<<AB, 256>>>(b1, batch);

    k_gemm<1><<<GB, 256, SMEM>>>(x, w2);
    k_premul<<<EB, 256>>>();
    k_aggregate<0><<<AB, 256>>>(b2, batch);

    k_gemm<1><<<GB, 256, SMEM>>>(x, w3);
    k_premul<<<EB, 256>>>();
    k_aggregate<1><<<AB, 256>>>(b3, batch);

    k_final<<<N_GRAPHS, 32>>>(lw, lb, out);
}

// round 15
// speedup vs baseline: 1.0542x; 1.0542x over previous
#include <cuda_runtime.h>
#include <cuda_bf16.h>
#include <stdint.h>

#define N_NODES  50000
#define N_EDGES  800000
#define F        128
#define N_GRAPHS 128
#define N_CLASSES 10

// ---------------- scratch (no allocations allowed) ----------------
__device__ __align__(16) float g_H[N_NODES * F];     // GEMM output
__device__ __align__(16) float g_ACC[N_NODES * F];   // aggregated layer output
__device__ float g_dinv[N_NODES];
__device__ int   g_degi[N_NODES];
__device__ int   g_rowbeg[N_NODES];
__device__ int   g_cursor[N_NODES];
__device__ int   g_alloc;
__device__ int   g_csrc[N_EDGES];
__device__ float g_cnorm[N_EDGES];
__device__ __align__(16) float g_gsum[N_GRAPHS * F];
__device__ float g_gcnt[N_GRAPHS];

__device__ __forceinline__ void red_add_v4(float* p, float4 v) {
    asm volatile("red.relaxed.gpu.global.add.v4.f32 [%0], {%1, %2, %3, %4};"
                 :: "l"(p), "f"(v.x), "f"(v.y), "f"(v.z), "f"(v.w)
                 : "memory");
}

// ---------------- packed f32x2 helpers (Blackwell FFMA2) ----------------
__device__ __forceinline__ unsigned long long pack2(float lo, float hi) {
    unsigned long long r;
    asm("mov.b64 %0, {%1, %2};" : "=l"(r) : "f"(lo), "f"(hi));
    return r;
}
__device__ __forceinline__ void fma2(unsigned long long& d,
                                     unsigned long long a, unsigned long long b) {
    asm("fma.rn.f32x2 %0, %1, %2, %0;" : "+l"(d) : "l"(a), "l"(b));
}
__device__ __forceinline__ float2 unpack2(unsigned long long v) {
    float2 r;
    asm("mov.b64 {%0, %1}, %2;" : "=f"(r.x), "=f"(r.y) : "l"(v));
    return r;
}

// ---------------- precompute ----------------
__global__ void k_init(const int* __restrict__ batch) {
    int i = blockIdx.x * blockDim.x + threadIdx.x;
    if (i < N_NODES) {
        g_degi[i] = 0;
        atomicAdd(&g_gcnt[batch[i]], 1.0f);
    }
    if (i < N_GRAPHS * F) g_gsum[i] = 0.0f;
    if (i == 0) g_alloc = 0;
}

__global__ void k_zero_cnt() {
    int i = threadIdx.x;
    if (i < N_GRAPHS) g_gcnt[i] = 0.0f;
}

__global__ void k_deg(const int* __restrict__ ei) {
    int e = blockIdx.x * blockDim.x + threadIdx.x;
    if (e < N_EDGES) atomicAdd(&g_degi[ei[N_EDGES + e]], 1);
}

// warp-aggregated segment allocation: one global atomic per warp
__global__ void k_alloc_seg() {
    int i    = blockIdx.x * blockDim.x + threadIdx.x;
    int lane = threadIdx.x & 31;
    int deg  = (i < N_NODES) ? g_degi[i] : 0;
    int scan = deg;
    #pragma unroll
    for (int o = 1; o < 32; o <<= 1) {
        int t = __shfl_up_sync(0xFFFFFFFFu, scan, o);
        if (lane >= o) scan += t;
    }
    int total = __shfl_sync(0xFFFFFFFFu, scan, 31);
    int base = 0;
    if (lane == 31) base = atomicAdd(&g_alloc, total);
    base = __shfl_sync(0xFFFFFFFFu, base, 31);
    if (i < N_NODES) {
        int pos = base + scan - deg;
        g_rowbeg[i] = pos;
        g_cursor[i] = pos;
        g_dinv[i]   = rsqrtf((float)deg + 1.0f);
    }
}

__global__ void k_fill(const int* __restrict__ ei) {
    int e = blockIdx.x * blockDim.x + threadIdx.x;
    if (e < N_EDGES) {
        int s = ei[e];
        int d = ei[N_EDGES + e];
        int pos = atomicAdd(&g_cursor[d], 1);
        g_csrc[pos]  = s;
        g_cnorm[pos] = g_dinv[s] * g_dinv[d];
    }
}

// ---------------- GEMM: H = act(X) @ W  (FFMA2, zipped row-pair X) ----------
// MODE 0: read Xin (no relu). MODE 1: read relu(g_ACC).
// Block: 64 rows x 128 cols, 256 threads, full K=128 in smem (96 KB, 2 CTA/SM).
template <int MODE>
__global__ void __launch_bounds__(256, 2)
k_gemm(const float* __restrict__ Xin, const float* __restrict__ W) {
    extern __shared__ float smem[];
    float* sW  = smem;            // [128][128] = 64 KB
    float* sXz = smem + F * F;    // [32 rp][128 k][2] = 32 KB

    const int tid  = threadIdx.x;
    const int row0 = blockIdx.x * 64;

    #pragma unroll
    for (int i = 0; i < 16; i++)
        ((float4*)sW)[tid + i * 256] = ((const float4*)W)[tid + i * 256];

    const float* src = (MODE == 0) ? Xin : g_ACC;
    #pragma unroll
    for (int i = 0; i < 4; i++) {
        int idx = tid + i * 256;          // over 32 k4-groups x 32 row-pairs
        int k4  = idx & 31;
        int rp  = idx >> 5;
        int r0  = row0 + 2 * rp;
        float4 a = make_float4(0.f, 0.f, 0.f, 0.f);
        float4 b = make_float4(0.f, 0.f, 0.f, 0.f);
        if (r0 < N_NODES)     a = ((const float4*)(src + (size_t)r0 * F))[k4];
        if (r0 + 1 < N_NODES) b = ((const float4*)(src + (size_t)(r0 + 1) * F))[k4];
        if (MODE == 1) {
            a.x = fmaxf(a.x, 0.f); a.y = fmaxf(a.y, 0.f);
            a.z = fmaxf(a.z, 0.f); a.w = fmaxf(a.w, 0.f);
            b.x = fmaxf(b.x, 0.f); b.y = fmaxf(b.y, 0.f);
            b.z = fmaxf(b.z, 0.f); b.w = fmaxf(b.w, 0.f);
        }
        float2* dst = (float2*)&sXz[rp * 256 + k4 * 8];
        dst[0] = make_float2(a.x, b.x);
        dst[1] = make_float2(a.y, b.y);
        dst[2] = make_float2(a.z, b.z);
        dst[3] = make_float2(a.w, b.w);
    }
    __syncthreads();

    const int wp = tid >> 5;     // warp 0..7 -> row-pairs 4wp..4wp+3
    const int cg = tid & 31;     // lane -> cols 4cg..4cg+3

    unsigned long long acc[4][4];   // [row-pair][col], pair over rows
    #pragma unroll
    for (int i = 0; i < 4; i++)
        #pragma unroll
        for (int j = 0; j < 4; j++) acc[i][j] = 0ull;

    #pragma unroll 8
    for (int k = 0; k < F; k += 2) {
        float4 wa = *(float4*)&sW[k * F + cg * 4];
        float4 wb = *(float4*)&sW[(k + 1) * F + cg * 4];
        unsigned long long wa0 = pack2(wa.x, wa.x), wa1 = pack2(wa.y, wa.y);
        unsigned long long wa2 = pack2(wa.z, wa.z), wa3 = pack2(wa.w, wa.w);
        unsigned long long wb0 = pack2(wb.x, wb.x), wb1 = pack2(wb.y, wb.y);
        unsigned long long wb2 = pack2(wb.z, wb.z), wb3 = pack2(wb.w, wb.w);
        #pragma unroll
        for (int rp = 0; rp < 4; rp++) {
            ulonglong2 xp = *(const ulonglong2*)&sXz[(4 * wp + rp) * 256 + k * 2];
            fma2(acc[rp][0], xp.x, wa0); fma2(acc[rp][1], xp.x, wa1);
            fma2(acc[rp][2], xp.x, wa2); fma2(acc[rp][3], xp.x, wa3);
            fma2(acc[rp][0], xp.y, wb0); fma2(acc[rp][1], xp.y, wb1);
            fma2(acc[rp][2], xp.y, wb2); fma2(acc[rp][3], xp.y, wb3);
        }
    }

    #pragma unroll
    for (int rp = 0; rp < 4; rp++) {
        int r = row0 + 2 * (4 * wp + rp);
        float2 p0 = unpack2(acc[rp][0]);
        float2 p1 = unpack2(acc[rp][1]);
        float2 p2 = unpack2(acc[rp][2]);
        float2 p3 = unpack2(acc[rp][3]);
        if (r < N_NODES)
            *(float4*)&g_H[(size_t)r * F + cg * 4] =
                make_float4(p0.x, p1.x, p2.x, p3.x);
        if (r + 1 < N_NODES)
            *(float4*)&g_H[(size_t)(r + 1) * F + cg * 4] =
                make_float4(p0.y, p1.y, p2.y, p3.y);
    }
}

// ---------------- aggregate: ACC[d] = sum_in norm*H[s] + dinv[d]^2*H[d] + b ----
// Dual-chain 2-ahead pipeline: 4 gathers in flight per warp (MLP=4).
// POOL=1: RED the result into g_gsum[batch[d]] instead of storing ACC.
template <int POOL>
__global__ void __launch_bounds__(256)
k_aggregate(const float* __restrict__ bias, const int* __restrict__ batch) {
    const int warp = (blockIdx.x * blockDim.x + threadIdx.x) >> 5;
    const int lane = threadIdx.x & 31;
    if (warp >= N_NODES) return;
    const int d = warp;

    const int beg = __ldg(&g_rowbeg[d]);
    const int end = beg + __ldg(&g_degi[d]);
    const float di = __ldg(&g_dinv[d]);

    // chain A starts with the self-loop contribution
    float4 accA = *(const float4*)&g_H[(size_t)d * F + lane * 4];
    float sn = di * di;
    accA.x *= sn; accA.y *= sn; accA.z *= sn; accA.w *= sn;
    float4 accB = make_float4(0.f, 0.f, 0.f, 0.f);

    int j = beg;
    if (end - beg >= 2) {
        int   sA = __ldg(&g_csrc[j]);
        int   sB = __ldg(&g_csrc[j + 1]);
        float nA = __ldg(&g_cnorm[j]);
        float nB = __ldg(&g_cnorm[j + 1]);
        float4 vA = *(const float4*)&g_H[(size_t)sA * F + lane * 4];
        float4 vB = *(const float4*)&g_H[(size_t)sB * F + lane * 4];
        j += 2;
        for (; j + 1 < end; j += 2) {
            int   sA2 = __ldg(&g_csrc[j]);
            int   sB2 = __ldg(&g_csrc[j + 1]);
            float nA2 = __ldg(&g_cnorm[j]);
            float nB2 = __ldg(&g_cnorm[j + 1]);
            float4 vA2 = *(const float4*)&g_H[(size_t)sA2 * F + lane * 4];
            float4 vB2 = *(const float4*)&g_H[(size_t)sB2 * F + lane * 4];
            accA.x += nA * vA.x; accA.y += nA * vA.y;
            accA.z += nA * vA.z; accA.w += nA * vA.w;
            accB.x += nB * vB.x; accB.y += nB * vB.y;
            accB.z += nB * vB.z; accB.w += nB * vB.w;
            vA = vA2; nA = nA2; vB = vB2; nB = nB2;
        }
        accA.x += nA * vA.x; accA.y += nA * vA.y;
        accA.z += nA * vA.z; accA.w += nA * vA.w;
        accB.x += nB * vB.x; accB.y += nB * vB.y;
        accB.z += nB * vB.z; accB.w += nB * vB.w;
    }
    if (j < end) {                      // odd remainder edge
        int   s = __ldg(&g_csrc[j]);
        float nn = __ldg(&g_cnorm[j]);
        float4 v = *(const float4*)&g_H[(size_t)s * F + lane * 4];
        accA.x += nn * v.x; accA.y += nn * v.y;
        accA.z += nn * v.z; accA.w += nn * v.w;
    }

    float4 bv = *(const float4*)&bias[lane * 4];
    float4 acc = make_float4(accA.x + accB.x + bv.x,
                             accA.y + accB.y + bv.y,
                             accA.z + accB.z + bv.z,
                             accA.w + accB.w + bv.w);

    if (POOL) {
        int g = __ldg(&batch[d]);
        red_add_v4(&g_gsum[g * F + lane * 4], acc);
    } else {
        *(float4*)&g_ACC[(size_t)d * F + lane * 4] = acc;
    }
}

// ---------------- head ----------------
__global__ void k_final(const float* __restrict__ lin_w,
                        const float* __restrict__ lin_b,
                        float* __restrict__ out) {
    int g = blockIdx.x;
    int c = threadIdx.x;
    if (c >= N_CLASSES) return;
    float cnt = fmaxf(g_gcnt[g], 1.0f);
    float acc = 0.f;
    #pragma unroll 8
    for (int f = 0; f < F; f++)
        acc += g_gsum[g * F + f] * __ldg(&lin_w[f * N_CLASSES + c]);
    out[g * N_CLASSES + c] = acc / cnt + lin_b[c];
}

// ---------------- host ----------------
extern "C" void kernel_launch(void* const* d_in, const int* in_sizes, int n_in,
                              void* d_out, int out_size) {
    const float* x     = (const float*)d_in[0];
    const int*   ei    = (const int*)d_in[1];
    const int*   batch = (const int*)d_in[2];
    const float* w1 = (const float*)d_in[3];
    const float* b1 = (const float*)d_in[4];
    const float* w2 = (const float*)d_in[5];
    const float* b2 = (const float*)d_in[6];
    const float* w3 = (const float*)d_in[7];
    const float* b3 = (const float*)d_in[8];
    const float* lw = (const float*)d_in[9];
    const float* lb = (const float*)d_in[10];
    float* out = (float*)d_out;

    const int SMEM = (F * F + 64 * F) * (int)sizeof(float);   // 96 KB
    cudaFuncSetAttribute(k_gemm<0>, cudaFuncAttributeMaxDynamicSharedMemorySize, SMEM);
    cudaFuncSetAttribute(k_gemm<1>, cudaFuncAttributeMaxDynamicSharedMemorySize, SMEM);

    const int GB = (N_NODES + 63) / 64;
    const int AB = (N_NODES + 7) / 8;
    const int EB = (N_EDGES + 255) / 256;

    k_zero_cnt<<<1, N_GRAPHS>>>();
    k_init<<<(N_NODES + 255) / 256, 256>>>(batch);
    k_deg<<<EB, 256>>>(ei);
    k_alloc_seg<<<(N_NODES + 255) / 256, 256>>>();
    k_fill<<<EB, 256>>>(ei);

    k_gemm<0><<<GB, 256, SMEM>>>(x, w1);
    k_aggregate<0><<<AB, 256>>>(b1, batch);
    k_gemm<1><<<GB, 256, SMEM>>>(x, w2);
    k_aggregate<0><<<AB, 256>>>(b2, batch);
    k_gemm<1><<<GB, 256, SMEM>>>(x, w3);
    k_aggregate<1><<<AB, 256>>>(b3, batch);

    k_final<<<N_GRAPHS, 32>>>(lw, lb, out);
}

// round 16
// speedup vs baseline: 1.1641x; 1.1042x over previous
#include <cuda_runtime.h>
#include <cuda_bf16.h>
#include <stdint.h>

#define N_NODES  50000
#define N_EDGES  800000
#define F        128
#define N_GRAPHS 128
#define N_CLASSES 10

// ---------------- scratch (no allocations allowed) ----------------
__device__ __align__(16) float g_H[N_NODES * F];     // GEMM output
__device__ __align__(16) float g_ACC[N_NODES * F];   // aggregated layer output
__device__ float g_dinv[N_NODES];
__device__ int   g_degi[N_NODES];
__device__ int   g_rowbeg[N_NODES];
__device__ int   g_cursor[N_NODES];
__device__ int   g_alloc;
__device__ int   g_csrc[N_EDGES];
__device__ float g_cnorm[N_EDGES];
__device__ __align__(16) float g_gsum[N_GRAPHS * F];

__device__ __forceinline__ void red_add_v4(float* p, float4 v) {
    asm volatile("red.relaxed.gpu.global.add.v4.f32 [%0], {%1, %2, %3, %4};"
                 :: "l"(p), "f"(v.x), "f"(v.y), "f"(v.z), "f"(v.w)
                 : "memory");
}

// ---------------- packed f32x2 helpers (Blackwell FFMA2) ----------------
__device__ __forceinline__ unsigned long long pack2(float lo, float hi) {
    unsigned long long r;
    asm("mov.b64 %0, {%1, %2};" : "=l"(r) : "f"(lo), "f"(hi));
    return r;
}
__device__ __forceinline__ void fma2(unsigned long long& d,
                                     unsigned long long a, unsigned long long b) {
    asm("fma.rn.f32x2 %0, %1, %2, %0;" : "+l"(d) : "l"(a), "l"(b));
}
__device__ __forceinline__ float2 unpack2(unsigned long long v) {
    float2 r;
    asm("mov.b64 {%0, %1}, %2;" : "=f"(r.x), "=f"(r.y) : "l"(v));
    return r;
}

// ---------------- precompute ----------------
__global__ void k_init() {
    int i = blockIdx.x * blockDim.x + threadIdx.x;
    if (i < N_NODES) g_degi[i] = 0;
    if (i < N_GRAPHS * F) g_gsum[i] = 0.0f;
    if (i == 0) g_alloc = 0;
}

__global__ void k_deg(const int* __restrict__ ei) {
    int e = blockIdx.x * blockDim.x + threadIdx.x;
    if (e < N_EDGES) atomicAdd(&g_degi[ei[N_EDGES + e]], 1);
}

// warp-aggregated segment allocation: one global atomic per warp
__global__ void k_alloc_seg() {
    int i    = blockIdx.x * blockDim.x + threadIdx.x;
    int lane = threadIdx.x & 31;
    int deg  = (i < N_NODES) ? g_degi[i] : 0;
    int scan = deg;
    #pragma unroll
    for (int o = 1; o < 32; o <<= 1) {
        int t = __shfl_up_sync(0xFFFFFFFFu, scan, o);
        if (lane >= o) scan += t;
    }
    int total = __shfl_sync(0xFFFFFFFFu, scan, 31);
    int base = 0;
    if (lane == 31) base = atomicAdd(&g_alloc, total);
    base = __shfl_sync(0xFFFFFFFFu, base, 31);
    if (i < N_NODES) {
        int pos = base + scan - deg;
        g_rowbeg[i] = pos;
        g_cursor[i] = pos;
        g_dinv[i]   = rsqrtf((float)deg + 1.0f);
    }
}

__global__ void k_fill(const int* __restrict__ ei) {
    int e = blockIdx.x * blockDim.x + threadIdx.x;
    if (e < N_EDGES) {
        int s = ei[e];
        int d = ei[N_EDGES + e];
        int pos = atomicAdd(&g_cursor[d], 1);
        g_csrc[pos]  = s;
        g_cnorm[pos] = g_dinv[s] * g_dinv[d];
    }
}

// ---------------- GEMM: H = act(X) @ W  (FFMA2, zipped row-pair X) ----------
// MODE 0: read Xin (no relu). MODE 1: read relu(g_ACC).
// Block: 64 rows x 128 cols, 256 threads, full K=128 in smem (96 KB, 2 CTA/SM).
template <int MODE>
__global__ void __launch_bounds__(256, 2)
k_gemm(const float* __restrict__ Xin, const float* __restrict__ W) {
    extern __shared__ float smem[];
    float* sW  = smem;            // [128][128] = 64 KB
    float* sXz = smem + F * F;    // [32 rp][128 k][2] = 32 KB

    const int tid  = threadIdx.x;
    const int row0 = blockIdx.x * 64;

    #pragma unroll
    for (int i = 0; i < 16; i++)
        ((float4*)sW)[tid + i * 256] = ((const float4*)W)[tid + i * 256];

    const float* src = (MODE == 0) ? Xin : g_ACC;
    #pragma unroll
    for (int i = 0; i < 4; i++) {
        int idx = tid + i * 256;          // over 32 k4-groups x 32 row-pairs
        int k4  = idx & 31;
        int rp  = idx >> 5;
        int r0  = row0 + 2 * rp;
        float4 a = make_float4(0.f, 0.f, 0.f, 0.f);
        float4 b = make_float4(0.f, 0.f, 0.f, 0.f);
        if (r0 < N_NODES)     a = ((const float4*)(src + (size_t)r0 * F))[k4];
        if (r0 + 1 < N_NODES) b = ((const float4*)(src + (size_t)(r0 + 1) * F))[k4];
        if (MODE == 1) {
            a.x = fmaxf(a.x, 0.f); a.y = fmaxf(a.y, 0.f);
            a.z = fmaxf(a.z, 0.f); a.w = fmaxf(a.w, 0.f);
            b.x = fmaxf(b.x, 0.f); b.y = fmaxf(b.y, 0.f);
            b.z = fmaxf(b.z, 0.f); b.w = fmaxf(b.w, 0.f);
        }
        float2* dst = (float2*)&sXz[rp * 256 + k4 * 8];
        dst[0] = make_float2(a.x, b.x);
        dst[1] = make_float2(a.y, b.y);
        dst[2] = make_float2(a.z, b.z);
        dst[3] = make_float2(a.w, b.w);
    }
    __syncthreads();

    const int wp = tid >> 5;     // warp 0..7 -> row-pairs 4wp..4wp+3
    const int cg = tid & 31;     // lane -> cols 4cg..4cg+3

    unsigned long long acc[4][4];   // [row-pair][col], pair over rows
    #pragma unroll
    for (int i = 0; i < 4; i++)
        #pragma unroll
        for (int j = 0; j < 4; j++) acc[i][j] = 0ull;

    #pragma unroll 4
    for (int k = 0; k < F; k += 2) {
        float4 wa = *(float4*)&sW[k * F + cg * 4];
        float4 wb = *(float4*)&sW[(k + 1) * F + cg * 4];
        unsigned long long wa0 = pack2(wa.x, wa.x), wa1 = pack2(wa.y, wa.y);
        unsigned long long wa2 = pack2(wa.z, wa.z), wa3 = pack2(wa.w, wa.w);
        unsigned long long wb0 = pack2(wb.x, wb.x), wb1 = pack2(wb.y, wb.y);
        unsigned long long wb2 = pack2(wb.z, wb.z), wb3 = pack2(wb.w, wb.w);
        #pragma unroll
        for (int rp = 0; rp < 4; rp++) {
            ulonglong2 xp = *(const ulonglong2*)&sXz[(4 * wp + rp) * 256 + k * 2];
            fma2(acc[rp][0], xp.x, wa0); fma2(acc[rp][1], xp.x, wa1);
            fma2(acc[rp][2], xp.x, wa2); fma2(acc[rp][3], xp.x, wa3);
            fma2(acc[rp][0], xp.y, wb0); fma2(acc[rp][1], xp.y, wb1);
            fma2(acc[rp][2], xp.y, wb2); fma2(acc[rp][3], xp.y, wb3);
        }
    }

    #pragma unroll
    for (int rp = 0; rp < 4; rp++) {
        int r = row0 + 2 * (4 * wp + rp);
        float2 p0 = unpack2(acc[rp][0]);
        float2 p1 = unpack2(acc[rp][1]);
        float2 p2 = unpack2(acc[rp][2]);
        float2 p3 = unpack2(acc[rp][3]);
        if (r < N_NODES)
            *(float4*)&g_H[(size_t)r * F + cg * 4] =
                make_float4(p0.x, p1.x, p2.x, p3.x);
        if (r + 1 < N_NODES)
            *(float4*)&g_H[(size_t)(r + 1) * F + cg * 4] =
                make_float4(p0.y, p1.y, p2.y, p3.y);
    }
}

// ---------------- aggregate: ACC[d] = sum_in norm*H[s] + dinv[d]^2*H[d] + b ----
// POOL=1: RED the result into g_gsum[batch[d]] instead of storing ACC.
template <int POOL>
__global__ void __launch_bounds__(256)
k_aggregate(const float* __restrict__ bias, const int* __restrict__ batch) {
    const int warp = (blockIdx.x * blockDim.x + threadIdx.x) >> 5;
    const int lane = threadIdx.x & 31;
    if (warp >= N_NODES) return;
    const int d = warp;

    const int beg = __ldg(&g_rowbeg[d]);
    const int end = beg + __ldg(&g_degi[d]);
    const float di = __ldg(&g_dinv[d]);

    float4 acc = *(const float4*)&g_H[(size_t)d * F + lane * 4];
    float sn = di * di;
    acc.x *= sn; acc.y *= sn; acc.z *= sn; acc.w *= sn;

    int j = beg;
    if (j < end) {
        int   s0 = __ldg(&g_csrc[j]);
        float n0 = __ldg(&g_cnorm[j]);
        float4 v0 = *(const float4*)&g_H[(size_t)s0 * F + lane * 4];
        for (j = beg + 1; j < end; j++) {
            int   s1 = __ldg(&g_csrc[j]);
            float n1 = __ldg(&g_cnorm[j]);
            float4 v1 = *(const float4*)&g_H[(size_t)s1 * F + lane * 4];
            acc.x += n0 * v0.x; acc.y += n0 * v0.y;
            acc.z += n0 * v0.z; acc.w += n0 * v0.w;
            v0 = v1; n0 = n1;
        }
        acc.x += n0 * v0.x; acc.y += n0 * v0.y;
        acc.z += n0 * v0.z; acc.w += n0 * v0.w;
    }

    float4 bv = *(const float4*)&bias[lane * 4];
    acc.x += bv.x; acc.y += bv.y; acc.z += bv.z; acc.w += bv.w;

    if (POOL) {
        int g = __ldg(&batch[d]);
        red_add_v4(&g_gsum[g * F + lane * 4], acc);
    } else {
        *(float4*)&g_ACC[(size_t)d * F + lane * 4] = acc;
    }
}

// ---------------- head: counts from sorted batch_ids via binary search ------
__global__ void k_final(const int* __restrict__ batch,
                        const float* __restrict__ lin_w,
                        const float* __restrict__ lin_b,
                        float* __restrict__ out) {
    int g = blockIdx.x;
    int c = threadIdx.x;
    __shared__ float s_cnt;
    if (c == 0) {
        int lo = 0, hi = N_NODES;               // lower_bound(g)
        while (lo < hi) { int m = (lo + hi) >> 1; if (__ldg(&batch[m]) < g) lo = m + 1; else hi = m; }
        int lo2 = lo, hi2 = N_NODES;            // upper_bound(g)
        while (lo2 < hi2) { int m = (lo2 + hi2) >> 1; if (__ldg(&batch[m]) <= g) lo2 = m + 1; else hi2 = m; }
        s_cnt = (float)(lo2 - lo);
    }
    __syncthreads();
    if (c >= N_CLASSES) return;
    float cnt = fmaxf(s_cnt, 1.0f);
    float acc = 0.f;
    #pragma unroll 8
    for (int f = 0; f < F; f++)
        acc += g_gsum[g * F + f] * __ldg(&lin_w[f * N_CLASSES + c]);
    out[g * N_CLASSES + c] = acc / cnt + lin_b[c];
}

// ---------------- host ----------------
extern "C" void kernel_launch(void* const* d_in, const int* in_sizes, int n_in,
                              void* d_out, int out_size) {
    const float* x     = (const float*)d_in[0];
    const int*   ei    = (const int*)d_in[1];
    const int*   batch = (const int*)d_in[2];
    const float* w1 = (const float*)d_in[3];
    const float* b1 = (const float*)d_in[4];
    const float* w2 = (const float*)d_in[5];
    const float* b2 = (const float*)d_in[6];
    const float* w3 = (const float*)d_in[7];
    const float* b3 = (const float*)d_in[8];
    const float* lw = (const float*)d_in[9];
    const float* lb = (const float*)d_in[10];
    float* out = (float*)d_out;

    static bool         s_ready = false;
    static cudaStream_t s_side;
    static cudaEvent_t  s_fork, s_join;
    if (!s_ready) {
        cudaStreamCreateWithFlags(&s_side, cudaStreamNonBlocking);
        cudaEventCreateWithFlags(&s_fork, cudaEventDisableTiming);
        cudaEventCreateWithFlags(&s_join, cudaEventDisableTiming);
        s_ready = true;
    }

    const int SMEM = (F * F + 64 * F) * (int)sizeof(float);   // 96 KB
    cudaFuncSetAttribute(k_gemm<0>, cudaFuncAttributeMaxDynamicSharedMemorySize, SMEM);
    cudaFuncSetAttribute(k_gemm<1>, cudaFuncAttributeMaxDynamicSharedMemorySize, SMEM);

    const int GB = (N_NODES + 63) / 64;
    const int AB = (N_NODES + 7) / 8;
    const int EB = (N_EDGES + 255) / 256;
    const int NB = (N_NODES + 255) / 256;

    // fork: CSR build on side stream, concurrent with layer-1 GEMM
    cudaEventRecord(s_fork, 0);
    cudaStreamWaitEvent(s_side, s_fork, 0);
    k_init<<<NB, 256, 0, s_side>>>();
    k_deg<<<EB, 256, 0, s_side>>>(ei);
    k_alloc_seg<<<NB, 256, 0, s_side>>>();
    k_fill<<<EB, 256, 0, s_side>>>(ei);
    cudaEventRecord(s_join, s_side);

    k_gemm<0><<<GB, 256, SMEM>>>(x, w1);      // needs only x, w1

    cudaStreamWaitEvent(0, s_join, 0);        // CSR ready before aggregates
    k_aggregate<0><<<AB, 256>>>(b1, batch);
    k_gemm<1><<<GB, 256, SMEM>>>(x, w2);
    k_aggregate<0><<<AB, 256>>>(b2, batch);
    k_gemm<1><<<GB, 256, SMEM>>>(x, w3);
    k_aggregate<1><<<AB, 256>>>(b3, batch);   // fused mean-pool accumulation

    k_final<<<N_GRAPHS, 32>>>(batch, lw, lb, out);
}